// round 1
// baseline (speedup 1.0000x reference)
#include <cuda_runtime.h>
#include <cuda_bf16.h>
#include <cstdint>
#include <cstddef>

// Problem constants (fixed by the reference's setup_inputs)
#define BB    16
#define LQ    1024
#define EMBED 768
#define NH    12
#define NL    3
#define NP    4
#define DV    384
#define DH    32
#define LKV   5376   // 64*64 + 32*32 + 16*16

// ---------------- scratch (device globals; no allocation) ----------------
__device__ float g_value[(size_t)BB * LKV * NH * DH];     // 33,030,144 f  (132 MB)
__device__ float g_off  [(size_t)BB * LQ * NH * NL * NP * 2]; // 4,718,592 f
__device__ float g_aw   [(size_t)BB * LQ * NH * NL * NP];     // 2,359,296 f
__device__ float g_attn [(size_t)BB * LQ * DV];               // 6,291,456 f
__device__ float g_qstats [(size_t)BB * LQ * 2];
__device__ float g_kvstats[(size_t)BB * LKV * 2];

// ---------------- row mean/rstd for fused LayerNorm ----------------
__global__ void row_stats_kernel(const float* __restrict__ X,
                                 float* __restrict__ stats, int K) {
    int row = blockIdx.x;
    const float* x = X + (size_t)row * K;
    float s = 0.f, sq = 0.f;
    for (int i = threadIdx.x; i < K; i += blockDim.x) {
        float v = x[i];
        s += v; sq += v * v;
    }
    // warp reduce
    for (int o = 16; o > 0; o >>= 1) {
        s  += __shfl_down_sync(0xffffffffu, s,  o);
        sq += __shfl_down_sync(0xffffffffu, sq, o);
    }
    __shared__ float shs[8], shq[8];
    int wid = threadIdx.x >> 5, lane = threadIdx.x & 31;
    if (lane == 0) { shs[wid] = s; shq[wid] = sq; }
    __syncthreads();
    if (threadIdx.x == 0) {
        float ts = 0.f, tq = 0.f;
        #pragma unroll
        for (int i = 0; i < 8; i++) { ts += shs[i]; tq += shq[i]; }
        float mean = ts / (float)K;
        float var  = tq / (float)K - mean * mean;
        float rstd = rsqrtf(var + 1e-6f);
        stats[2 * row + 0] = mean;
        stats[2 * row + 1] = rstd;
    }
}

// ---------------- SGEMM with optional fused LayerNorm on A ----------------
// MODE 0: A is LN(raw A) via (stats, lnw, lnb);   C = acc + bias
// MODE 1: A plain;   C = resid + gamma * (acc + bias)
template <int MODE>
__global__ void __launch_bounds__(256, 2)
gemm_ln_kernel(const float* __restrict__ A, const float* __restrict__ Bm,
               float* __restrict__ C, int M, int N, int K,
               const float* __restrict__ stats,
               const float* __restrict__ lnw, const float* __restrict__ lnb,
               const float* __restrict__ bias,
               const float* __restrict__ resid, const float* __restrict__ gamma) {
    constexpr int BM = 128, BN = 64, BK = 16;
    __shared__ float As[BK][BM];
    __shared__ float Bs[BK][BN];

    const int tid = threadIdx.x;
    const int tx = tid & 15;        // col group (4 cols)
    const int ty = tid >> 4;        // row group (8 rows)
    const int row0 = blockIdx.y * BM;
    const int n0   = blockIdx.x * BN;

    // A-tile load geometry (c fixed per thread since 256 % 16 == 0)
    const int cA = tid & 15;
    const int rA = tid >> 4;        // rows rA + i*16, i in [0,8)
    // B-tile load geometry (c fixed since 256 % 64 == 0)
    const int cB = tid & 63;
    const int rB = tid >> 6;        // rows rB + i*4, i in [0,4)
    const int colB = n0 + cB;
    const bool colBok = (colB < N);

    float mu[8], rs[8];
    if (MODE == 0) {
        #pragma unroll
        for (int i = 0; i < 8; i++) {
            int grow = row0 + rA + i * 16;
            mu[i] = stats[2 * grow + 0];
            rs[i] = stats[2 * grow + 1];
        }
    }

    float acc[8][4];
    #pragma unroll
    for (int i = 0; i < 8; i++)
        #pragma unroll
        for (int j = 0; j < 4; j++) acc[i][j] = 0.f;

    for (int k0 = 0; k0 < K; k0 += BK) {
        float w_ln = 0.f, b_ln = 0.f;
        if (MODE == 0) { w_ln = lnw[k0 + cA]; b_ln = lnb[k0 + cA]; }
        #pragma unroll
        for (int i = 0; i < 8; i++) {
            int grow = row0 + rA + i * 16;
            float v = A[(size_t)grow * K + k0 + cA];
            if (MODE == 0) v = (v - mu[i]) * rs[i] * w_ln + b_ln;
            As[cA][rA + i * 16] = v;
        }
        #pragma unroll
        for (int i = 0; i < 4; i++) {
            int kr = k0 + rB + i * 4;
            Bs[rB + i * 4][cB] = colBok ? Bm[(size_t)kr * N + colB] : 0.f;
        }
        __syncthreads();

        #pragma unroll
        for (int kk = 0; kk < BK; kk++) {
            float a[8], bb[4];
            #pragma unroll
            for (int i = 0; i < 8; i++) a[i] = As[kk][ty * 8 + i];
            #pragma unroll
            for (int j = 0; j < 4; j++) bb[j] = Bs[kk][tx * 4 + j];
            #pragma unroll
            for (int i = 0; i < 8; i++)
                #pragma unroll
                for (int j = 0; j < 4; j++)
                    acc[i][j] = fmaf(a[i], bb[j], acc[i][j]);
        }
        __syncthreads();
    }

    #pragma unroll
    for (int i = 0; i < 8; i++) {
        int row = row0 + ty * 8 + i;
        #pragma unroll
        for (int j = 0; j < 4; j++) {
            int col = n0 + tx * 4 + j;
            if (col < N) {
                float v = acc[i][j] + bias[col];
                if (MODE == 1)
                    v = resid[(size_t)row * N + col] + gamma[col] * v;
                C[(size_t)row * N + col] = v;
            }
        }
    }
}

// ---------------- deformable bilinear sampling ----------------
// One warp per (b, q, head); lane = channel d in [0, 32).
__global__ void __launch_bounds__(256)
sample_kernel(const float* __restrict__ value,  // (B, LKV, NH, DH)
              const float* __restrict__ off,    // (B*LQ, NH*NL*NP*2)
              const float* __restrict__ aw,     // (B*LQ, NH*NL*NP) logits
              const float* __restrict__ refp,   // (B*LQ, NL, 2)
              float* __restrict__ attn)         // (B*LQ, NH*DH)
{
    int gw = (blockIdx.x * blockDim.x + threadIdx.x) >> 5;
    int lane = threadIdx.x & 31;
    const int NWARP = BB * LQ * NH;
    if (gw >= NWARP) return;
    int h  = gw % NH;
    int bq = gw / NH;
    int b  = bq >> 10;   // LQ = 1024

    // softmax over the 12 (level, point) logits
    const float* lgp = aw + (size_t)gw * (NL * NP);
    float lg[NL * NP];
    float mx = -1e30f;
    #pragma unroll
    for (int i = 0; i < NL * NP; i++) { lg[i] = lgp[i]; mx = fmaxf(mx, lg[i]); }
    float ssum = 0.f;
    #pragma unroll
    for (int i = 0; i < NL * NP; i++) { lg[i] = expf(lg[i] - mx); ssum += lg[i]; }
    float inv = 1.0f / ssum;

    const float* op = off + (size_t)gw * (NL * NP * 2);
    const float* rp = refp + (size_t)bq * (NL * 2);

    const int Hs[3] = {64, 32, 16};
    const int Ws[3] = {64, 32, 16};
    const int St[3] = {0, 4096, 5120};

    float acc = 0.f;
    #pragma unroll
    for (int l = 0; l < NL; l++) {
        const int H = Hs[l], W = Ws[l], st = St[l];
        const float rx = rp[l * 2 + 0], ry = rp[l * 2 + 1];
        const float* vb = value + ((((size_t)b * LKV + st) * NH + h) * DH) + lane;
        #pragma unroll
        for (int p = 0; p < NP; p++) {
            float ox = op[(l * NP + p) * 2 + 0];
            float oy = op[(l * NP + p) * 2 + 1];
            float locx = rx + ox / (float)W;
            float locy = ry + oy / (float)H;
            float xx = locx * (float)W - 0.5f;
            float yy = locy * (float)H - 0.5f;
            float x0f = floorf(xx), y0f = floorf(yy);
            float dx = xx - x0f, dy = yy - y0f;
            int x0 = (int)x0f, y0 = (int)y0f;
            float wgt = lg[l * NP + p] * inv;
            float w00 = (1.f - dx) * (1.f - dy) * wgt;
            float w01 = dx * (1.f - dy) * wgt;
            float w10 = (1.f - dx) * dy * wgt;
            float w11 = dx * dy * wgt;
            int xs[4] = {x0, x0 + 1, x0, x0 + 1};
            int ys[4] = {y0, y0, y0 + 1, y0 + 1};
            float ws[4] = {w00, w01, w10, w11};
            #pragma unroll
            for (int c = 0; c < 4; c++) {
                if (xs[c] >= 0 && xs[c] < W && ys[c] >= 0 && ys[c] < H)
                    acc += ws[c] * vb[(size_t)(ys[c] * W + xs[c]) * (NH * DH)];
            }
        }
    }
    attn[(size_t)gw * DH + lane] = acc;
}

// ---------------- launch ----------------
extern "C" void kernel_launch(void* const* d_in, const int* in_sizes, int n_in,
                              void* d_out, int out_size) {
    const float* q      = (const float*)d_in[0];
    const float* refp   = (const float*)d_in[1];
    const float* kv     = (const float*)d_in[2];
    // d_in[3] spatial_shapes, d_in[4] level_start_index: constants, unused
    const float* ln1w   = (const float*)d_in[5];
    const float* ln1b   = (const float*)d_in[6];
    const float* ln2w   = (const float*)d_in[7];
    const float* ln2b   = (const float*)d_in[8];
    const float* gamma  = (const float*)d_in[9];
    const float* w_off  = (const float*)d_in[10];
    const float* b_off  = (const float*)d_in[11];
    const float* w_aw   = (const float*)d_in[12];
    const float* b_aw   = (const float*)d_in[13];
    const float* w_val  = (const float*)d_in[14];
    const float* b_val  = (const float*)d_in[15];
    const float* w_out  = (const float*)d_in[16];
    const float* b_out  = (const float*)d_in[17];
    float* out = (float*)d_out;

    float *gv, *goff, *gaw, *gattn, *gqs, *gks;
    cudaGetSymbolAddress((void**)&gv,    g_value);
    cudaGetSymbolAddress((void**)&goff,  g_off);
    cudaGetSymbolAddress((void**)&gaw,   g_aw);
    cudaGetSymbolAddress((void**)&gattn, g_attn);
    cudaGetSymbolAddress((void**)&gqs,   g_qstats);
    cudaGetSymbolAddress((void**)&gks,   g_kvstats);

    const int Mq  = BB * LQ;    // 16384
    const int Mkv = BB * LKV;   // 86016

    // LayerNorm statistics
    row_stats_kernel<<<Mq, 256>>>(q, gqs, EMBED);
    row_stats_kernel<<<Mkv, 256>>>(kv, gks, EMBED);

    // value = LN(kv) @ w_val + b_val     (86016 x 384, K=768)
    gemm_ln_kernel<0><<<dim3(DV / 64, Mkv / 128), 256>>>(
        kv, w_val, gv, Mkv, DV, EMBED, gks, ln2w, ln2b, b_val, nullptr, nullptr);

    // off = LN(q) @ w_off + b_off        (16384 x 288)
    gemm_ln_kernel<0><<<dim3((288 + 63) / 64, Mq / 128), 256>>>(
        q, w_off, goff, Mq, 288, EMBED, gqs, ln1w, ln1b, b_off, nullptr, nullptr);

    // aw logits = LN(q) @ w_aw + b_aw    (16384 x 144)
    gemm_ln_kernel<0><<<dim3((144 + 63) / 64, Mq / 128), 256>>>(
        q, w_aw, gaw, Mq, 144, EMBED, gqs, ln1w, ln1b, b_aw, nullptr, nullptr);

    // deformable sampling: one warp per (b,q,head)
    {
        int nwarp = BB * LQ * NH;           // 196608
        int blocks = nwarp / 8;             // 8 warps / block
        sample_kernel<<<blocks, 256>>>(gv, goff, gaw, refp, gattn);
    }

    // out = q + gamma * (attn @ w_out + b_out)   (16384 x 768, K=384)
    gemm_ln_kernel<1><<<dim3(EMBED / 64, Mq / 128), 256>>>(
        gattn, w_out, out, Mq, EMBED, DV, nullptr, nullptr, nullptr,
        b_out, q, gamma);
}

// round 2
// speedup vs baseline: 3.3717x; 3.3717x over previous
#include <cuda_runtime.h>
#include <cuda_bf16.h>
#include <cstdint>
#include <cstddef>

#define BB    16
#define LQ    1024
#define EMBED 768
#define NH    12
#define NL    3
#define NP    4
#define DV    384
#define DH    32
#define LKV   5376

// ---------------- scratch (device globals; no allocation) ----------------
__device__ __nv_bfloat16 g_value[(size_t)BB * LKV * NH * DH];   // 66 MB bf16
__device__ float g_off  [(size_t)BB * LQ * NH * NL * NP * 2];
__device__ float g_aw   [(size_t)BB * LQ * NH * NL * NP];
__device__ float g_attn [(size_t)BB * LQ * DV];
__device__ float g_qstats [(size_t)BB * LQ * 2];
__device__ float g_kvstats[(size_t)BB * LKV * 2];

// ---------------- row mean/rstd for fused LayerNorm ----------------
__global__ void row_stats_kernel(const float* __restrict__ X,
                                 float* __restrict__ stats, int K) {
    int row = blockIdx.x;
    const float* x = X + (size_t)row * K;
    float s = 0.f, sq = 0.f;
    for (int i = threadIdx.x; i < K; i += blockDim.x) {
        float v = x[i];
        s += v; sq += v * v;
    }
    for (int o = 16; o > 0; o >>= 1) {
        s  += __shfl_down_sync(0xffffffffu, s,  o);
        sq += __shfl_down_sync(0xffffffffu, sq, o);
    }
    __shared__ float shs[8], shq[8];
    int wid = threadIdx.x >> 5, lane = threadIdx.x & 31;
    if (lane == 0) { shs[wid] = s; shq[wid] = sq; }
    __syncthreads();
    if (threadIdx.x == 0) {
        float ts = 0.f, tq = 0.f;
        #pragma unroll
        for (int i = 0; i < 8; i++) { ts += shs[i]; tq += shq[i]; }
        float mean = ts / (float)K;
        float var  = tq / (float)K - mean * mean;
        float rstd = rsqrtf(var + 1e-6f);
        stats[2 * row + 0] = mean;
        stats[2 * row + 1] = rstd;
    }
}

// ---------------- tensor-core GEMM helpers ----------------
__device__ __forceinline__ void ldsm_x4(uint32_t& r0, uint32_t& r1,
                                        uint32_t& r2, uint32_t& r3, uint32_t addr) {
    asm volatile("ldmatrix.sync.aligned.m8n8.x4.shared.b16 {%0,%1,%2,%3}, [%4];"
                 : "=r"(r0), "=r"(r1), "=r"(r2), "=r"(r3) : "r"(addr));
}
__device__ __forceinline__ void ldsm_x4_t(uint32_t& r0, uint32_t& r1,
                                          uint32_t& r2, uint32_t& r3, uint32_t addr) {
    asm volatile("ldmatrix.sync.aligned.m8n8.x4.trans.shared.b16 {%0,%1,%2,%3}, [%4];"
                 : "=r"(r0), "=r"(r1), "=r"(r2), "=r"(r3) : "r"(addr));
}
__device__ __forceinline__ void mma_bf16(float* c, const uint32_t* a,
                                         uint32_t b0, uint32_t b1) {
    asm volatile(
        "mma.sync.aligned.m16n8k16.row.col.f32.bf16.bf16.f32 "
        "{%0,%1,%2,%3}, {%4,%5,%6,%7}, {%8,%9}, {%0,%1,%2,%3};"
        : "+f"(c[0]), "+f"(c[1]), "+f"(c[2]), "+f"(c[3])
        : "r"(a[0]), "r"(a[1]), "r"(a[2]), "r"(a[3]), "r"(b0), "r"(b1));
}

#define SA 40    // padded A smem row stride (bf16 elems) -> 80 B, 16B-aligned, conflict-free
#define SB 136   // padded B smem row stride -> 272 B, 16B-aligned, conflict-free

// MODE 0: A = LN(rawA) (stats,lnw,lnb); C fp32 = acc + bias
// MODE 1: A plain fp32;                 C fp32 = resid + gamma*(acc + bias)
// MODE 2: A = LN(rawA);                 C bf16 = acc + bias
template <int MODE>
__global__ void __launch_bounds__(256)
hgemm_kernel(const float* __restrict__ A, const float* __restrict__ Bm,
             void* __restrict__ Cout, int M, int N, int K,
             const float* __restrict__ stats,
             const float* __restrict__ lnw, const float* __restrict__ lnb,
             const float* __restrict__ bias,
             const float* __restrict__ resid, const float* __restrict__ gamma) {
    __shared__ __align__(16) __nv_bfloat16 sA[2][128 * SA];
    __shared__ __align__(16) __nv_bfloat16 sB[2][32 * SB];

    const int tid  = threadIdx.x;
    const int lane = tid & 31;
    const int wid  = tid >> 5;
    const int wm   = wid & 3;      // warp row (32 rows each)
    const int wn   = wid >> 2;     // warp col (64 cols each)
    const int row0 = blockIdx.y * 128;
    const int n0   = blockIdx.x * 128;

    const int ac4 = tid & 7;       // A: col group of 4 within 32-wide k tile
    const int bc4 = tid & 31;      // B: col group of 4 within 128-wide n tile

    float acc[2][8][4];
    #pragma unroll
    for (int mt = 0; mt < 2; mt++)
        #pragma unroll
        for (int n8 = 0; n8 < 8; n8++)
            #pragma unroll
            for (int j = 0; j < 4; j++) acc[mt][n8][j] = 0.f;

    const int NT = K >> 5;

    auto load_tile = [&](int buf, int kt) {
        const int k0 = kt * 32;
        // ---- A tile: 128 x 32 fp32 -> LN -> bf16 ----
        #pragma unroll
        for (int i = 0; i < 4; i++) {
            int row  = (tid >> 3) + i * 32;
            int grow = row0 + row;
            float4 v4 = *(const float4*)(A + (size_t)grow * K + k0 + ac4 * 4);
            if (MODE != 1) {
                float mu = stats[2 * grow], rs = stats[2 * grow + 1];
                float4 w4 = *(const float4*)(lnw + k0 + ac4 * 4);
                float4 b4 = *(const float4*)(lnb + k0 + ac4 * 4);
                v4.x = (v4.x - mu) * rs * w4.x + b4.x;
                v4.y = (v4.y - mu) * rs * w4.y + b4.y;
                v4.z = (v4.z - mu) * rs * w4.z + b4.z;
                v4.w = (v4.w - mu) * rs * w4.w + b4.w;
            }
            __nv_bfloat162 p0 = __float22bfloat162_rn(make_float2(v4.x, v4.y));
            __nv_bfloat162 p1 = __float22bfloat162_rn(make_float2(v4.z, v4.w));
            uint2 pk = make_uint2(*(uint32_t*)&p0, *(uint32_t*)&p1);
            *(uint2*)(&sA[buf][row * SA + ac4 * 4]) = pk;
        }
        // ---- B tile: 32 x 128 fp32 -> bf16 (zero-fill OOB cols) ----
        #pragma unroll
        for (int i = 0; i < 4; i++) {
            int row = (tid >> 5) + i * 8;
            int col = n0 + bc4 * 4;
            float4 v4 = make_float4(0.f, 0.f, 0.f, 0.f);
            if (col < N)
                v4 = *(const float4*)(Bm + (size_t)(k0 + row) * N + col);
            __nv_bfloat162 p0 = __float22bfloat162_rn(make_float2(v4.x, v4.y));
            __nv_bfloat162 p1 = __float22bfloat162_rn(make_float2(v4.z, v4.w));
            uint2 pk = make_uint2(*(uint32_t*)&p0, *(uint32_t*)&p1);
            *(uint2*)(&sB[buf][row * SB + bc4 * 4]) = pk;
        }
    };

    const int lr  = lane & 15;
    const int lc8 = (lane >> 4) << 3;   // 0 or 8

    load_tile(0, 0);
    __syncthreads();

    for (int kt = 0; kt < NT; kt++) {
        int cur = kt & 1;
        if (kt + 1 < NT) load_tile(cur ^ 1, kt + 1);

        uint32_t sAb = (uint32_t)__cvta_generic_to_shared(&sA[cur][0]);
        uint32_t sBb = (uint32_t)__cvta_generic_to_shared(&sB[cur][0]);

        #pragma unroll
        for (int ks = 0; ks < 2; ks++) {
            const int kcol = ks * 16;
            uint32_t a[2][4];
            #pragma unroll
            for (int mt = 0; mt < 2; mt++) {
                uint32_t addr = sAb +
                    ((wm * 32 + mt * 16 + lr) * SA + kcol + lc8) * 2;
                ldsm_x4(a[mt][0], a[mt][1], a[mt][2], a[mt][3], addr);
            }
            uint32_t b[4][4];
            #pragma unroll
            for (int nt = 0; nt < 4; nt++) {
                uint32_t addr = sBb +
                    ((kcol + lr) * SB + wn * 64 + nt * 16 + lc8) * 2;
                ldsm_x4_t(b[nt][0], b[nt][1], b[nt][2], b[nt][3], addr);
            }
            #pragma unroll
            for (int mt = 0; mt < 2; mt++)
                #pragma unroll
                for (int n8 = 0; n8 < 8; n8++)
                    mma_bf16(acc[mt][n8], a[mt],
                             b[n8 >> 1][(n8 & 1) * 2], b[n8 >> 1][(n8 & 1) * 2 + 1]);
        }
        __syncthreads();
    }

    // ---- epilogue ----
    #pragma unroll
    for (int mt = 0; mt < 2; mt++) {
        int r = row0 + wm * 32 + mt * 16 + (lane >> 2);
        #pragma unroll
        for (int n8 = 0; n8 < 8; n8++) {
            int c = n0 + wn * 64 + n8 * 8 + (lane & 3) * 2;
            if (c >= N) continue;
            float2 bs = *(const float2*)(bias + c);
            float v0 = acc[mt][n8][0] + bs.x;
            float v1 = acc[mt][n8][1] + bs.y;
            float v2 = acc[mt][n8][2] + bs.x;
            float v3 = acc[mt][n8][3] + bs.y;
            if (MODE == 1) {
                float2 gm = *(const float2*)(gamma + c);
                float2 r0v = *(const float2*)(resid + (size_t)r * N + c);
                float2 r1v = *(const float2*)(resid + (size_t)(r + 8) * N + c);
                float* Cf = (float*)Cout;
                *(float2*)(Cf + (size_t)r * N + c) =
                    make_float2(r0v.x + gm.x * v0, r0v.y + gm.y * v1);
                *(float2*)(Cf + (size_t)(r + 8) * N + c) =
                    make_float2(r1v.x + gm.x * v2, r1v.y + gm.y * v3);
            } else if (MODE == 2) {
                __nv_bfloat16* Cb = (__nv_bfloat16*)Cout;
                *(__nv_bfloat162*)(Cb + (size_t)r * N + c) =
                    __float22bfloat162_rn(make_float2(v0, v1));
                *(__nv_bfloat162*)(Cb + (size_t)(r + 8) * N + c) =
                    __float22bfloat162_rn(make_float2(v2, v3));
            } else {
                float* Cf = (float*)Cout;
                *(float2*)(Cf + (size_t)r * N + c) = make_float2(v0, v1);
                *(float2*)(Cf + (size_t)(r + 8) * N + c) = make_float2(v2, v3);
            }
        }
    }
}

// ---------------- deformable bilinear sampling (value in bf16) ----------------
__global__ void __launch_bounds__(256)
sample_kernel(const __nv_bfloat16* __restrict__ value,  // (B, LKV, NH, DH)
              const float* __restrict__ off,    // (B*LQ, NH*NL*NP*2)
              const float* __restrict__ aw,     // (B*LQ, NH*NL*NP) logits
              const float* __restrict__ refp,   // (B*LQ, NL, 2)
              float* __restrict__ attn)         // (B*LQ, NH*DH)
{
    int gw = (blockIdx.x * blockDim.x + threadIdx.x) >> 5;
    int lane = threadIdx.x & 31;
    const int NWARP = BB * LQ * NH;
    if (gw >= NWARP) return;
    int h  = gw % NH;
    int bq = gw / NH;
    int b  = bq >> 10;   // LQ = 1024

    const float* lgp = aw + (size_t)gw * (NL * NP);
    float lg[NL * NP];
    float mx = -1e30f;
    #pragma unroll
    for (int i = 0; i < NL * NP; i++) { lg[i] = lgp[i]; mx = fmaxf(mx, lg[i]); }
    float ssum = 0.f;
    #pragma unroll
    for (int i = 0; i < NL * NP; i++) { lg[i] = __expf(lg[i] - mx); ssum += lg[i]; }
    float inv = 1.0f / ssum;

    const float* op = off + (size_t)gw * (NL * NP * 2);
    const float* rp = refp + (size_t)bq * (NL * 2);

    const int Hs[3] = {64, 32, 16};
    const int Ws[3] = {64, 32, 16};
    const int St[3] = {0, 4096, 5120};

    float acc = 0.f;
    #pragma unroll
    for (int l = 0; l < NL; l++) {
        const int H = Hs[l], W = Ws[l], st = St[l];
        const float rx = rp[l * 2 + 0], ry = rp[l * 2 + 1];
        const __nv_bfloat16* vb =
            value + ((((size_t)b * LKV + st) * NH + h) * DH) + lane;
        #pragma unroll
        for (int p = 0; p < NP; p++) {
            float ox = op[(l * NP + p) * 2 + 0];
            float oy = op[(l * NP + p) * 2 + 1];
            float xx = (rx + ox / (float)W) * (float)W - 0.5f;
            float yy = (ry + oy / (float)H) * (float)H - 0.5f;
            float x0f = floorf(xx), y0f = floorf(yy);
            float dx = xx - x0f, dy = yy - y0f;
            int x0 = (int)x0f, y0 = (int)y0f;
            float wgt = lg[l * NP + p] * inv;
            float w00 = (1.f - dx) * (1.f - dy) * wgt;
            float w01 = dx * (1.f - dy) * wgt;
            float w10 = (1.f - dx) * dy * wgt;
            float w11 = dx * dy * wgt;
            int xs[4] = {x0, x0 + 1, x0, x0 + 1};
            int ys[4] = {y0, y0, y0 + 1, y0 + 1};
            float ws[4] = {w00, w01, w10, w11};
            #pragma unroll
            for (int c = 0; c < 4; c++) {
                if (xs[c] >= 0 && xs[c] < W && ys[c] >= 0 && ys[c] < H)
                    acc += ws[c] * __bfloat162float(
                        vb[(size_t)(ys[c] * W + xs[c]) * (NH * DH)]);
            }
        }
    }
    attn[(size_t)gw * DH + lane] = acc;
}

// ---------------- launch ----------------
extern "C" void kernel_launch(void* const* d_in, const int* in_sizes, int n_in,
                              void* d_out, int out_size) {
    const float* q      = (const float*)d_in[0];
    const float* refp   = (const float*)d_in[1];
    const float* kv     = (const float*)d_in[2];
    const float* ln1w   = (const float*)d_in[5];
    const float* ln1b   = (const float*)d_in[6];
    const float* ln2w   = (const float*)d_in[7];
    const float* ln2b   = (const float*)d_in[8];
    const float* gamma  = (const float*)d_in[9];
    const float* w_off  = (const float*)d_in[10];
    const float* b_off  = (const float*)d_in[11];
    const float* w_aw   = (const float*)d_in[12];
    const float* b_aw   = (const float*)d_in[13];
    const float* w_val  = (const float*)d_in[14];
    const float* b_val  = (const float*)d_in[15];
    const float* w_out  = (const float*)d_in[16];
    const float* b_out  = (const float*)d_in[17];
    float* out = (float*)d_out;

    __nv_bfloat16* gv;
    float *goff, *gaw, *gattn, *gqs, *gks;
    cudaGetSymbolAddress((void**)&gv,    g_value);
    cudaGetSymbolAddress((void**)&goff,  g_off);
    cudaGetSymbolAddress((void**)&gaw,   g_aw);
    cudaGetSymbolAddress((void**)&gattn, g_attn);
    cudaGetSymbolAddress((void**)&gqs,   g_qstats);
    cudaGetSymbolAddress((void**)&gks,   g_kvstats);

    const int Mq  = BB * LQ;    // 16384
    const int Mkv = BB * LKV;   // 86016

    row_stats_kernel<<<Mq, 256>>>(q, gqs, EMBED);
    row_stats_kernel<<<Mkv, 256>>>(kv, gks, EMBED);

    // value = LN(kv) @ w_val + b_val  -> bf16   (86016 x 384, K=768)
    hgemm_kernel<2><<<dim3((DV + 127) / 128, Mkv / 128), 256>>>(
        kv, w_val, gv, Mkv, DV, EMBED, gks, ln2w, ln2b, b_val, nullptr, nullptr);

    // off = LN(q) @ w_off + b_off     (16384 x 288, K=768)
    hgemm_kernel<0><<<dim3((288 + 127) / 128, Mq / 128), 256>>>(
        q, w_off, goff, Mq, 288, EMBED, gqs, ln1w, ln1b, b_off, nullptr, nullptr);

    // aw logits = LN(q) @ w_aw + b_aw (16384 x 144, K=768)
    hgemm_kernel<0><<<dim3((144 + 127) / 128, Mq / 128), 256>>>(
        q, w_aw, gaw, Mq, 144, EMBED, gqs, ln1w, ln1b, b_aw, nullptr, nullptr);

    // deformable sampling
    {
        int nwarp = BB * LQ * NH;   // 196608
        sample_kernel<<<nwarp / 8, 256>>>(gv, goff, gaw, refp, gattn);
    }

    // out = q + gamma * (attn @ w_out + b_out)  (16384 x 768, K=384)
    hgemm_kernel<1><<<dim3(EMBED / 128, Mq / 128), 256>>>(
        gattn, w_out, out, Mq, EMBED, DV, nullptr, nullptr, nullptr,
        b_out, q, gamma);
}

// round 3
// speedup vs baseline: 4.7898x; 1.4206x over previous
#include <cuda_runtime.h>
#include <cuda_bf16.h>
#include <cstdint>
#include <cstddef>

#define BB    16
#define LQ    1024
#define EMBED 768
#define NH    12
#define NL    3
#define NP    4
#define DV    384
#define DH    32
#define LKV   5376
#define NOFF  288
#define NAW   144
#define NPK   432   // packed off+aw columns

// ---------------- scratch (device globals; no allocation) ----------------
__device__ __nv_bfloat16 g_qn   [(size_t)BB * LQ  * EMBED];
__device__ __nv_bfloat16 g_kvn  [(size_t)BB * LKV * EMBED];
__device__ __nv_bfloat16 g_value[(size_t)BB * LKV * DV];
__device__ float         g_offaw[(size_t)BB * LQ  * NPK];
__device__ __nv_bfloat16 g_attn [(size_t)BB * LQ  * DV];
__device__ __nv_bfloat16 g_wv[EMBED * DV];
__device__ __nv_bfloat16 g_wc[EMBED * NPK];
__device__ __nv_bfloat16 g_wo[DV * EMBED];
__device__ float         g_bc[NPK];

// ---------------- fused LayerNorm -> bf16 (K = 768 fixed) ----------------
__global__ void __launch_bounds__(256)
ln_bf16_kernel(const float* __restrict__ X, __nv_bfloat16* __restrict__ Y,
               const float* __restrict__ w, const float* __restrict__ b) {
    int row = blockIdx.x;
    const float* x = X + (size_t)row * EMBED;
    float v[3];
    float s = 0.f, sq = 0.f;
    #pragma unroll
    for (int i = 0; i < 3; i++) {
        v[i] = x[threadIdx.x + i * 256];
        s += v[i]; sq += v[i] * v[i];
    }
    #pragma unroll
    for (int o = 16; o > 0; o >>= 1) {
        s  += __shfl_down_sync(0xffffffffu, s,  o);
        sq += __shfl_down_sync(0xffffffffu, sq, o);
    }
    __shared__ float shs[8], shq[8], smr[2];
    int wid = threadIdx.x >> 5, lane = threadIdx.x & 31;
    if (lane == 0) { shs[wid] = s; shq[wid] = sq; }
    __syncthreads();
    if (threadIdx.x == 0) {
        float ts = 0.f, tq = 0.f;
        #pragma unroll
        for (int i = 0; i < 8; i++) { ts += shs[i]; tq += shq[i]; }
        float mu = ts * (1.f / EMBED);
        float var = tq * (1.f / EMBED) - mu * mu;
        smr[0] = mu; smr[1] = rsqrtf(var + 1e-6f);
    }
    __syncthreads();
    float mu = smr[0], rs = smr[1];
    #pragma unroll
    for (int i = 0; i < 3; i++) {
        int c = threadIdx.x + i * 256;
        Y[(size_t)row * EMBED + c] =
            __float2bfloat16((v[i] - mu) * rs * w[c] + b[c]);
    }
}

// ---------------- weight conversion / packing ----------------
__global__ void cvt_kernel(const float* __restrict__ s,
                           __nv_bfloat16* __restrict__ d, int n) {
    int i = blockIdx.x * blockDim.x + threadIdx.x;
    if (i < n) d[i] = __float2bfloat16(s[i]);
}
__global__ void pack_kernel(const float* __restrict__ wo, const float* __restrict__ wa,
                            const float* __restrict__ bo, const float* __restrict__ ba,
                            __nv_bfloat16* __restrict__ d, float* __restrict__ bc) {
    int i = blockIdx.x * blockDim.x + threadIdx.x;
    if (i < EMBED * NPK) {
        int k = i / NPK, c = i % NPK;
        float v = (c < NOFF) ? wo[k * NOFF + c] : wa[k * NAW + c - NOFF];
        d[i] = __float2bfloat16(v);
    }
    if (i < NPK) bc[i] = (i < NOFF) ? bo[i] : ba[i - NOFF];
}

// ---------------- tensor-core GEMM ----------------
__device__ __forceinline__ void ldsm_x4(uint32_t& r0, uint32_t& r1,
                                        uint32_t& r2, uint32_t& r3, uint32_t addr) {
    asm volatile("ldmatrix.sync.aligned.m8n8.x4.shared.b16 {%0,%1,%2,%3}, [%4];"
                 : "=r"(r0), "=r"(r1), "=r"(r2), "=r"(r3) : "r"(addr));
}
__device__ __forceinline__ void ldsm_x4_t(uint32_t& r0, uint32_t& r1,
                                          uint32_t& r2, uint32_t& r3, uint32_t addr) {
    asm volatile("ldmatrix.sync.aligned.m8n8.x4.trans.shared.b16 {%0,%1,%2,%3}, [%4];"
                 : "=r"(r0), "=r"(r1), "=r"(r2), "=r"(r3) : "r"(addr));
}
__device__ __forceinline__ void mma_bf16(float* c, const uint32_t* a,
                                         uint32_t b0, uint32_t b1) {
    asm volatile(
        "mma.sync.aligned.m16n8k16.row.col.f32.bf16.bf16.f32 "
        "{%0,%1,%2,%3}, {%4,%5,%6,%7}, {%8,%9}, {%0,%1,%2,%3};"
        : "+f"(c[0]), "+f"(c[1]), "+f"(c[2]), "+f"(c[3])
        : "r"(a[0]), "r"(a[1]), "r"(a[2]), "r"(a[3]), "r"(b0), "r"(b1));
}
__device__ __forceinline__ void cp16(uint32_t s, const void* g) {
    asm volatile("cp.async.cg.shared.global [%0], [%1], 16;" :: "r"(s), "l"(g));
}
__device__ __forceinline__ void cp16z(uint32_t s, const void* g, bool pred) {
    int sz = pred ? 16 : 0;
    asm volatile("cp.async.cg.shared.global [%0], [%1], 16, %2;"
                 :: "r"(s), "l"(g), "r"(sz));
}
#define CP_COMMIT() asm volatile("cp.async.commit_group;")
template <int N>
__device__ __forceinline__ void cp_wait() {
    asm volatile("cp.async.wait_group %0;" :: "n"(N));
}

#define SA 40    // A smem row stride (bf16) -> 80 B
#define SB 136   // B smem row stride -> 272 B
#define STAGES 4
#define SMEM_BYTES ((STAGES * 128 * SA + STAGES * 32 * SB) * 2)

// MODE 0: C fp32 = acc + bias
// MODE 1: C fp32 = resid + gamma * (acc + bias)
// MODE 2: C bf16 = acc + bias
template <int MODE>
__global__ void __launch_bounds__(256, 2)
hgemm_kernel(const __nv_bfloat16* __restrict__ A,
             const __nv_bfloat16* __restrict__ Bm,
             void* __restrict__ Cout, int M, int N, int K,
             const float* __restrict__ bias,
             const float* __restrict__ resid, const float* __restrict__ gamma) {
    extern __shared__ __nv_bfloat16 smem[];
    __nv_bfloat16* sA = smem;                         // STAGES * 128 * SA
    __nv_bfloat16* sB = smem + STAGES * 128 * SA;     // STAGES * 32 * SB

    const int tid  = threadIdx.x;
    const int lane = tid & 31;
    const int wid  = tid >> 5;
    const int wm   = wid & 3;
    const int wn   = wid >> 2;
    const int row0 = blockIdx.y * 128;
    const int n0   = blockIdx.x * 128;
    const int NT   = K >> 5;

    const uint32_t sAbase = (uint32_t)__cvta_generic_to_shared(sA);
    const uint32_t sBbase = (uint32_t)__cvta_generic_to_shared(sB);

    auto load_tile = [&](int stage, int kt) {
        const int k0 = kt * 32;
        #pragma unroll
        for (int j = 0; j < 2; j++) {
            int ci = tid * 2 + j;
            int ar = ci >> 2, ac = (ci & 3) * 8;
            cp16(sAbase + (uint32_t)(stage * 128 * SA + ar * SA + ac) * 2,
                 A + (size_t)(row0 + ar) * K + k0 + ac);
            int br = ci >> 4, bc = (ci & 15) * 8;
            int col = n0 + bc;
            cp16z(sBbase + (uint32_t)(stage * 32 * SB + br * SB + bc) * 2,
                  Bm + (size_t)(k0 + br) * N + col, col < N);
        }
    };

    float acc[2][8][4];
    #pragma unroll
    for (int mt = 0; mt < 2; mt++)
        #pragma unroll
        for (int n8 = 0; n8 < 8; n8++)
            #pragma unroll
            for (int j = 0; j < 4; j++) acc[mt][n8][j] = 0.f;

    #pragma unroll
    for (int s = 0; s < STAGES - 1; s++) {
        if (s < NT) load_tile(s, s);
        CP_COMMIT();
    }

    const int lr  = lane & 15;
    const int lc8 = (lane >> 4) << 3;

    for (int kt = 0; kt < NT; kt++) {
        cp_wait<STAGES - 2>();
        __syncthreads();
        if (kt + STAGES - 1 < NT)
            load_tile((kt + STAGES - 1) % STAGES, kt + STAGES - 1);
        CP_COMMIT();

        const int cur = kt % STAGES;
        const uint32_t sAb = sAbase + (uint32_t)(cur * 128 * SA) * 2;
        const uint32_t sBb = sBbase + (uint32_t)(cur * 32 * SB) * 2;

        #pragma unroll
        for (int ks = 0; ks < 2; ks++) {
            const int kcol = ks * 16;
            uint32_t a[2][4];
            #pragma unroll
            for (int mt = 0; mt < 2; mt++) {
                uint32_t addr = sAb +
                    (uint32_t)((wm * 32 + mt * 16 + lr) * SA + kcol + lc8) * 2;
                ldsm_x4(a[mt][0], a[mt][1], a[mt][2], a[mt][3], addr);
            }
            uint32_t b[4][4];
            #pragma unroll
            for (int nt = 0; nt < 4; nt++) {
                uint32_t addr = sBb +
                    (uint32_t)((kcol + lr) * SB + wn * 64 + nt * 16 + lc8) * 2;
                ldsm_x4_t(b[nt][0], b[nt][1], b[nt][2], b[nt][3], addr);
            }
            #pragma unroll
            for (int mt = 0; mt < 2; mt++)
                #pragma unroll
                for (int n8 = 0; n8 < 8; n8++)
                    mma_bf16(acc[mt][n8], a[mt],
                             b[n8 >> 1][(n8 & 1) * 2], b[n8 >> 1][(n8 & 1) * 2 + 1]);
        }
    }

    // ---- epilogue ----
    #pragma unroll
    for (int mt = 0; mt < 2; mt++) {
        int r = row0 + wm * 32 + mt * 16 + (lane >> 2);
        #pragma unroll
        for (int n8 = 0; n8 < 8; n8++) {
            int c = n0 + wn * 64 + n8 * 8 + (lane & 3) * 2;
            if (c >= N) continue;
            float2 bs = *(const float2*)(bias + c);
            float v0 = acc[mt][n8][0] + bs.x;
            float v1 = acc[mt][n8][1] + bs.y;
            float v2 = acc[mt][n8][2] + bs.x;
            float v3 = acc[mt][n8][3] + bs.y;
            if (MODE == 1) {
                float2 gm = *(const float2*)(gamma + c);
                float2 r0v = *(const float2*)(resid + (size_t)r * N + c);
                float2 r1v = *(const float2*)(resid + (size_t)(r + 8) * N + c);
                float* Cf = (float*)Cout;
                *(float2*)(Cf + (size_t)r * N + c) =
                    make_float2(r0v.x + gm.x * v0, r0v.y + gm.y * v1);
                *(float2*)(Cf + (size_t)(r + 8) * N + c) =
                    make_float2(r1v.x + gm.x * v2, r1v.y + gm.y * v3);
            } else if (MODE == 2) {
                __nv_bfloat16* Cb = (__nv_bfloat16*)Cout;
                *(__nv_bfloat162*)(Cb + (size_t)r * N + c) =
                    __float22bfloat162_rn(make_float2(v0, v1));
                *(__nv_bfloat162*)(Cb + (size_t)(r + 8) * N + c) =
                    __float22bfloat162_rn(make_float2(v2, v3));
            } else {
                float* Cf = (float*)Cout;
                *(float2*)(Cf + (size_t)r * N + c) = make_float2(v0, v1);
                *(float2*)(Cf + (size_t)(r + 8) * N + c) = make_float2(v2, v3);
            }
        }
    }
}

// ---------------- deformable bilinear sampling ----------------
// One warp per (b, q, head); lane = channel d in [0, 32).
__global__ void __launch_bounds__(256)
sample_kernel(const __nv_bfloat16* __restrict__ value,  // (B, LKV, NH, DH)
              const float* __restrict__ offaw,  // (B*LQ, 432) packed
              const float* __restrict__ refp,   // (B*LQ, NL, 2)
              __nv_bfloat16* __restrict__ attn) // (B*LQ, NH*DH)
{
    int gw = (blockIdx.x * blockDim.x + threadIdx.x) >> 5;
    int lane = threadIdx.x & 31;
    const int NWARP = BB * LQ * NH;
    if (gw >= NWARP) return;
    int h  = gw % NH;
    int bq = gw / NH;
    int b  = bq >> 10;

    const float* rowp = offaw + (size_t)bq * NPK;
    const float* lgp = rowp + NOFF + h * (NL * NP);
    const float* op  = rowp + h * (NL * NP * 2);

    float lg[NL * NP];
    float mx = -1e30f;
    #pragma unroll
    for (int i = 0; i < NL * NP; i++) { lg[i] = lgp[i]; mx = fmaxf(mx, lg[i]); }
    float ssum = 0.f;
    #pragma unroll
    for (int i = 0; i < NL * NP; i++) { lg[i] = __expf(lg[i] - mx); ssum += lg[i]; }
    float inv = 1.0f / ssum;

    const float* rp = refp + (size_t)bq * (NL * 2);

    const int Hs[3] = {64, 32, 16};
    const int Ws[3] = {64, 32, 16};
    const int St[3] = {0, 4096, 5120};

    float acc = 0.f;
    #pragma unroll
    for (int l = 0; l < NL; l++) {
        const int H = Hs[l], W = Ws[l], st = St[l];
        const float rx = rp[l * 2 + 0], ry = rp[l * 2 + 1];
        const __nv_bfloat16* vb =
            value + ((((size_t)b * LKV + st) * NH + h) * DH) + lane;
        #pragma unroll
        for (int p = 0; p < NP; p++) {
            float ox = op[(l * NP + p) * 2 + 0];
            float oy = op[(l * NP + p) * 2 + 1];
            float xx = (rx + ox / (float)W) * (float)W - 0.5f;
            float yy = (ry + oy / (float)H) * (float)H - 0.5f;
            float x0f = floorf(xx), y0f = floorf(yy);
            float dx = xx - x0f, dy = yy - y0f;
            int x0 = (int)x0f, y0 = (int)y0f;
            float wgt = lg[l * NP + p] * inv;
            float w00 = (1.f - dx) * (1.f - dy) * wgt;
            float w01 = dx * (1.f - dy) * wgt;
            float w10 = (1.f - dx) * dy * wgt;
            float w11 = dx * dy * wgt;
            int xs[4] = {x0, x0 + 1, x0, x0 + 1};
            int ys[4] = {y0, y0, y0 + 1, y0 + 1};
            float ws[4] = {w00, w01, w10, w11};
            #pragma unroll
            for (int c = 0; c < 4; c++) {
                if (xs[c] >= 0 && xs[c] < W && ys[c] >= 0 && ys[c] < H)
                    acc += ws[c] * __bfloat162float(
                        vb[(size_t)(ys[c] * W + xs[c]) * (NH * DH)]);
            }
        }
    }
    attn[(size_t)gw * DH + lane] = __float2bfloat16(acc);
}

// ---------------- launch ----------------
extern "C" void kernel_launch(void* const* d_in, const int* in_sizes, int n_in,
                              void* d_out, int out_size) {
    const float* q      = (const float*)d_in[0];
    const float* refp   = (const float*)d_in[1];
    const float* kv     = (const float*)d_in[2];
    const float* ln1w   = (const float*)d_in[5];
    const float* ln1b   = (const float*)d_in[6];
    const float* ln2w   = (const float*)d_in[7];
    const float* ln2b   = (const float*)d_in[8];
    const float* gamma  = (const float*)d_in[9];
    const float* w_off  = (const float*)d_in[10];
    const float* b_off  = (const float*)d_in[11];
    const float* w_aw   = (const float*)d_in[12];
    const float* b_aw   = (const float*)d_in[13];
    const float* w_val  = (const float*)d_in[14];
    const float* b_val  = (const float*)d_in[15];
    const float* w_out  = (const float*)d_in[16];
    const float* b_out  = (const float*)d_in[17];
    float* out = (float*)d_out;

    __nv_bfloat16 *gqn, *gkvn, *gv, *gattn, *gwv, *gwc, *gwo;
    float *goffaw, *gbc;
    cudaGetSymbolAddress((void**)&gqn,    g_qn);
    cudaGetSymbolAddress((void**)&gkvn,   g_kvn);
    cudaGetSymbolAddress((void**)&gv,     g_value);
    cudaGetSymbolAddress((void**)&goffaw, g_offaw);
    cudaGetSymbolAddress((void**)&gattn,  g_attn);
    cudaGetSymbolAddress((void**)&gwv,    g_wv);
    cudaGetSymbolAddress((void**)&gwc,    g_wc);
    cudaGetSymbolAddress((void**)&gwo,    g_wo);
    cudaGetSymbolAddress((void**)&gbc,    g_bc);

    static bool attr_done = false;
    if (!attr_done) {
        cudaFuncSetAttribute(hgemm_kernel<0>,
            cudaFuncAttributeMaxDynamicSharedMemorySize, SMEM_BYTES);
        cudaFuncSetAttribute(hgemm_kernel<1>,
            cudaFuncAttributeMaxDynamicSharedMemorySize, SMEM_BYTES);
        cudaFuncSetAttribute(hgemm_kernel<2>,
            cudaFuncAttributeMaxDynamicSharedMemorySize, SMEM_BYTES);
        attr_done = true;
    }

    const int Mq  = BB * LQ;    // 16384
    const int Mkv = BB * LKV;   // 86016

    // LN -> bf16
    ln_bf16_kernel<<<Mq, 256>>>(q, gqn, ln1w, ln1b);
    ln_bf16_kernel<<<Mkv, 256>>>(kv, gkvn, ln2w, ln2b);

    // weights -> bf16 (+ pack off/aw)
    cvt_kernel<<<(EMBED * DV + 255) / 256, 256>>>(w_val, gwv, EMBED * DV);
    pack_kernel<<<(EMBED * NPK + 255) / 256, 256>>>(w_off, w_aw, b_off, b_aw, gwc, gbc);
    cvt_kernel<<<(DV * EMBED + 255) / 256, 256>>>(w_out, gwo, DV * EMBED);

    // value = kvn @ wv + b_val  -> bf16   (86016 x 384, K=768)
    hgemm_kernel<2><<<dim3(DV / 128, Mkv / 128), 256, SMEM_BYTES>>>(
        gkvn, gwv, gv, Mkv, DV, EMBED, b_val, nullptr, nullptr);

    // [off | aw] = qn @ wc + bc  (16384 x 432, K=768)
    hgemm_kernel<0><<<dim3((NPK + 127) / 128, Mq / 128), 256, SMEM_BYTES>>>(
        gqn, gwc, goffaw, Mq, NPK, EMBED, gbc, nullptr, nullptr);

    // deformable sampling -> bf16 attn
    sample_kernel<<<(BB * LQ * NH) / 8, 256>>>(gv, goffaw, refp, gattn);

    // out = q + gamma * (attn @ wo + b_out)  (16384 x 768, K=384)
    hgemm_kernel<1><<<dim3(EMBED / 128, Mq / 128), 256, SMEM_BYTES>>>(
        gattn, gwo, out, Mq, EMBED, DV, b_out, q, gamma);
}

// round 4
// speedup vs baseline: 6.0213x; 1.2571x over previous
#include <cuda_runtime.h>
#include <cuda_bf16.h>
#include <cstdint>
#include <cstddef>

#define BB    16
#define LQ    1024
#define EMBED 768
#define NH    12
#define NL    3
#define NP    4
#define DV    384
#define DH    32
#define LKV   5376
#define NOFF  288
#define NAW   144
#define NPK   432

// ---------------- scratch (device globals; no allocation) ----------------
__device__ __nv_bfloat16 g_qn   [(size_t)BB * LQ  * EMBED];
__device__ __nv_bfloat16 g_kvn  [(size_t)BB * LKV * EMBED];
__device__ __nv_bfloat16 g_value[(size_t)BB * LKV * DV];
__device__ float         g_offaw[(size_t)BB * LQ  * NPK];
__device__ __nv_bfloat16 g_attn [(size_t)BB * LQ  * DV];
__device__ __nv_bfloat16 g_wv[EMBED * DV];
__device__ __nv_bfloat16 g_wc[EMBED * NPK];
__device__ __nv_bfloat16 g_wo[DV * EMBED];
__device__ float         g_bc[NPK];

// ---------------- fused LayerNorm -> bf16 (row = 768, 192 thr) ----------------
__global__ void __launch_bounds__(192)
ln_bf16_kernel(const float* __restrict__ X, __nv_bfloat16* __restrict__ Y,
               const float* __restrict__ w, const float* __restrict__ b) {
    int row = blockIdx.x;
    int tid = threadIdx.x;
    float4 v = ((const float4*)(X + (size_t)row * EMBED))[tid];
    float s  = v.x + v.y + v.z + v.w;
    float sq = v.x * v.x + v.y * v.y + v.z * v.z + v.w * v.w;
    #pragma unroll
    for (int o = 16; o > 0; o >>= 1) {
        s  += __shfl_down_sync(0xffffffffu, s,  o);
        sq += __shfl_down_sync(0xffffffffu, sq, o);
    }
    __shared__ float shs[6], shq[6];
    int wid = tid >> 5, lane = tid & 31;
    if (lane == 0) { shs[wid] = s; shq[wid] = sq; }
    __syncthreads();
    float ts = 0.f, tq = 0.f;
    #pragma unroll
    for (int i = 0; i < 6; i++) { ts += shs[i]; tq += shq[i]; }
    float mu = ts * (1.f / EMBED);
    float var = tq * (1.f / EMBED) - mu * mu;
    float rs = rsqrtf(var + 1e-6f);
    float4 w4 = ((const float4*)w)[tid];
    float4 b4 = ((const float4*)b)[tid];
    __nv_bfloat162 p0 = __float22bfloat162_rn(make_float2(
        (v.x - mu) * rs * w4.x + b4.x, (v.y - mu) * rs * w4.y + b4.y));
    __nv_bfloat162 p1 = __float22bfloat162_rn(make_float2(
        (v.z - mu) * rs * w4.z + b4.z, (v.w - mu) * rs * w4.w + b4.w));
    uint2 pk = make_uint2(*(uint32_t*)&p0, *(uint32_t*)&p1);
    ((uint2*)(Y + (size_t)row * EMBED))[tid] = pk;
}

// ---------------- weight conversion / packing ----------------
__global__ void cvt_kernel(const float* __restrict__ s,
                           __nv_bfloat16* __restrict__ d, int n) {
    int i = blockIdx.x * blockDim.x + threadIdx.x;
    if (i < n) d[i] = __float2bfloat16(s[i]);
}
__global__ void pack_kernel(const float* __restrict__ wo, const float* __restrict__ wa,
                            const float* __restrict__ bo, const float* __restrict__ ba,
                            __nv_bfloat16* __restrict__ d, float* __restrict__ bc) {
    int i = blockIdx.x * blockDim.x + threadIdx.x;
    if (i < EMBED * NPK) {
        int k = i / NPK, c = i % NPK;
        float v = (c < NOFF) ? wo[k * NOFF + c] : wa[k * NAW + c - NOFF];
        d[i] = __float2bfloat16(v);
    }
    if (i < NPK) bc[i] = (i < NOFF) ? bo[i] : ba[i - NOFF];
}

// ---------------- tensor-core GEMM ----------------
__device__ __forceinline__ void ldsm_x4(uint32_t& r0, uint32_t& r1,
                                        uint32_t& r2, uint32_t& r3, uint32_t addr) {
    asm volatile("ldmatrix.sync.aligned.m8n8.x4.shared.b16 {%0,%1,%2,%3}, [%4];"
                 : "=r"(r0), "=r"(r1), "=r"(r2), "=r"(r3) : "r"(addr));
}
__device__ __forceinline__ void ldsm_x4_t(uint32_t& r0, uint32_t& r1,
                                          uint32_t& r2, uint32_t& r3, uint32_t addr) {
    asm volatile("ldmatrix.sync.aligned.m8n8.x4.trans.shared.b16 {%0,%1,%2,%3}, [%4];"
                 : "=r"(r0), "=r"(r1), "=r"(r2), "=r"(r3) : "r"(addr));
}
__device__ __forceinline__ void mma_bf16(float* c, const uint32_t* a,
                                         uint32_t b0, uint32_t b1) {
    asm volatile(
        "mma.sync.aligned.m16n8k16.row.col.f32.bf16.bf16.f32 "
        "{%0,%1,%2,%3}, {%4,%5,%6,%7}, {%8,%9}, {%0,%1,%2,%3};"
        : "+f"(c[0]), "+f"(c[1]), "+f"(c[2]), "+f"(c[3])
        : "r"(a[0]), "r"(a[1]), "r"(a[2]), "r"(a[3]), "r"(b0), "r"(b1));
}
__device__ __forceinline__ void cp16(uint32_t s, const void* g) {
    asm volatile("cp.async.cg.shared.global [%0], [%1], 16;" :: "r"(s), "l"(g));
}
__device__ __forceinline__ void cp16z(uint32_t s, const void* g, bool pred) {
    int sz = pred ? 16 : 0;
    asm volatile("cp.async.cg.shared.global [%0], [%1], 16, %2;"
                 :: "r"(s), "l"(g), "r"(sz));
}
#define CP_COMMIT() asm volatile("cp.async.commit_group;")
template <int N>
__device__ __forceinline__ void cp_wait() {
    asm volatile("cp.async.wait_group %0;" :: "n"(N));
}

#define SA 40
#define SB 136
#define STAGES 4
#define SMEM_BYTES ((STAGES * 128 * SA + STAGES * 32 * SB) * 2)

// MODE 0: C fp32 = acc + bias
// MODE 1: C fp32 = resid + gamma * (acc + bias)
// MODE 2: C bf16 = acc + bias
template <int MODE>
__global__ void __launch_bounds__(256, 2)
hgemm_kernel(const __nv_bfloat16* __restrict__ A,
             const __nv_bfloat16* __restrict__ Bm,
             void* __restrict__ Cout, int M, int N, int K,
             const float* __restrict__ bias,
             const float* __restrict__ resid, const float* __restrict__ gamma) {
    extern __shared__ __nv_bfloat16 smem[];
    __nv_bfloat16* sA = smem;
    __nv_bfloat16* sB = smem + STAGES * 128 * SA;

    const int tid  = threadIdx.x;
    const int lane = tid & 31;
    const int wid  = tid >> 5;
    const int wm   = wid & 3;
    const int wn   = wid >> 2;
    const int row0 = blockIdx.y * 128;
    const int n0   = blockIdx.x * 128;
    const int NT   = K >> 5;

    const uint32_t sAbase = (uint32_t)__cvta_generic_to_shared(sA);
    const uint32_t sBbase = (uint32_t)__cvta_generic_to_shared(sB);

    auto load_tile = [&](int stage, int kt) {
        const int k0 = kt * 32;
        #pragma unroll
        for (int j = 0; j < 2; j++) {
            int ci = tid * 2 + j;
            int ar = ci >> 2, ac = (ci & 3) * 8;
            cp16(sAbase + (uint32_t)(stage * 128 * SA + ar * SA + ac) * 2,
                 A + (size_t)(row0 + ar) * K + k0 + ac);
            int br = ci >> 4, bc = (ci & 15) * 8;
            int col = n0 + bc;
            cp16z(sBbase + (uint32_t)(stage * 32 * SB + br * SB + bc) * 2,
                  Bm + (size_t)(k0 + br) * N + col, col < N);
        }
    };

    float acc[2][8][4];
    #pragma unroll
    for (int mt = 0; mt < 2; mt++)
        #pragma unroll
        for (int n8 = 0; n8 < 8; n8++)
            #pragma unroll
            for (int j = 0; j < 4; j++) acc[mt][n8][j] = 0.f;

    #pragma unroll
    for (int s = 0; s < STAGES - 1; s++) {
        if (s < NT) load_tile(s, s);
        CP_COMMIT();
    }

    const int lr  = lane & 15;
    const int lc8 = (lane >> 4) << 3;

    for (int kt = 0; kt < NT; kt++) {
        cp_wait<STAGES - 2>();
        __syncthreads();
        if (kt + STAGES - 1 < NT)
            load_tile((kt + STAGES - 1) % STAGES, kt + STAGES - 1);
        CP_COMMIT();

        const int cur = kt % STAGES;
        const uint32_t sAb = sAbase + (uint32_t)(cur * 128 * SA) * 2;
        const uint32_t sBb = sBbase + (uint32_t)(cur * 32 * SB) * 2;

        #pragma unroll
        for (int ks = 0; ks < 2; ks++) {
            const int kcol = ks * 16;
            uint32_t a[2][4];
            #pragma unroll
            for (int mt = 0; mt < 2; mt++) {
                uint32_t addr = sAb +
                    (uint32_t)((wm * 32 + mt * 16 + lr) * SA + kcol + lc8) * 2;
                ldsm_x4(a[mt][0], a[mt][1], a[mt][2], a[mt][3], addr);
            }
            uint32_t b[4][4];
            #pragma unroll
            for (int nt = 0; nt < 4; nt++) {
                uint32_t addr = sBb +
                    (uint32_t)((kcol + lr) * SB + wn * 64 + nt * 16 + lc8) * 2;
                ldsm_x4_t(b[nt][0], b[nt][1], b[nt][2], b[nt][3], addr);
            }
            #pragma unroll
            for (int mt = 0; mt < 2; mt++)
                #pragma unroll
                for (int n8 = 0; n8 < 8; n8++)
                    mma_bf16(acc[mt][n8], a[mt],
                             b[n8 >> 1][(n8 & 1) * 2], b[n8 >> 1][(n8 & 1) * 2 + 1]);
        }
    }

    #pragma unroll
    for (int mt = 0; mt < 2; mt++) {
        int r = row0 + wm * 32 + mt * 16 + (lane >> 2);
        #pragma unroll
        for (int n8 = 0; n8 < 8; n8++) {
            int c = n0 + wn * 64 + n8 * 8 + (lane & 3) * 2;
            if (c >= N) continue;
            float2 bs = *(const float2*)(bias + c);
            float v0 = acc[mt][n8][0] + bs.x;
            float v1 = acc[mt][n8][1] + bs.y;
            float v2 = acc[mt][n8][2] + bs.x;
            float v3 = acc[mt][n8][3] + bs.y;
            if (MODE == 1) {
                float2 gm = *(const float2*)(gamma + c);
                float2 r0v = *(const float2*)(resid + (size_t)r * N + c);
                float2 r1v = *(const float2*)(resid + (size_t)(r + 8) * N + c);
                float* Cf = (float*)Cout;
                *(float2*)(Cf + (size_t)r * N + c) =
                    make_float2(r0v.x + gm.x * v0, r0v.y + gm.y * v1);
                *(float2*)(Cf + (size_t)(r + 8) * N + c) =
                    make_float2(r1v.x + gm.x * v2, r1v.y + gm.y * v3);
            } else if (MODE == 2) {
                __nv_bfloat16* Cb = (__nv_bfloat16*)Cout;
                *(__nv_bfloat162*)(Cb + (size_t)r * N + c) =
                    __float22bfloat162_rn(make_float2(v0, v1));
                *(__nv_bfloat162*)(Cb + (size_t)(r + 8) * N + c) =
                    __float22bfloat162_rn(make_float2(v2, v3));
            } else {
                float* Cf = (float*)Cout;
                *(float2*)(Cf + (size_t)r * N + c) = make_float2(v0, v1);
                *(float2*)(Cf + (size_t)(r + 8) * N + c) = make_float2(v2, v3);
            }
        }
    }
}

// ---------------- deformable bilinear sampling (8-wide corner MLP) ----------
// One warp per (b,q,h). lane>>2 = corner slot (8 parallel), lane&3 = 16B chunk
// of the 64B channel row (8 bf16 each). 48 corner tasks -> 6 iterations.
__global__ void __launch_bounds__(256)
sample_kernel(const __nv_bfloat16* __restrict__ value,  // (B, LKV, NH*DH)
              const float* __restrict__ offaw,          // (B*LQ, 432)
              const float* __restrict__ refp,           // (B*LQ, NL, 2)
              __nv_bfloat16* __restrict__ attn)         // (B*LQ, NH*DH)
{
    const int gw   = (blockIdx.x * blockDim.x + threadIdx.x) >> 5;
    const int lane = threadIdx.x & 31;
    const int cg   = lane >> 2;    // corner slot 0..7
    const int ch4  = lane & 3;     // 16B chunk
    const int h  = gw % NH;
    const int bq = gw / NH;
    const int b  = bq >> 10;

    const float* rowp = offaw + (size_t)bq * NPK;
    const float* lgp  = rowp + NOFF + h * (NL * NP);
    const float* op   = rowp + h * (NL * NP * 2);
    const float* rp   = refp + (size_t)bq * (NL * 2);

    // softmax denominator (redundant per lane; all loads L1-broadcast)
    float mx = -1e30f;
    #pragma unroll
    for (int i = 0; i < NL * NP; i++) mx = fmaxf(mx, lgp[i]);
    float ssum = 0.f;
    #pragma unroll
    for (int i = 0; i < NL * NP; i++) ssum += __expf(lgp[i] - mx);
    const float inv = 1.0f / ssum;

    float acc[8];
    #pragma unroll
    for (int j = 0; j < 8; j++) acc[j] = 0.f;

    const __nv_bfloat16* vbb = value + (size_t)b * LKV * DV + h * DH;

    #pragma unroll
    for (int i = 0; i < 6; i++) {
        const int t      = i * 8 + cg;
        const int corner = t & 3;
        const int pt     = t >> 2;       // 0..11
        const int l      = pt >> 2;      // 0..2
        const int W      = 64 >> l;      // H == W
        const int st     = (l == 0) ? 0 : ((l == 1) ? 4096 : 5120);

        const float rx = rp[l * 2 + 0], ry = rp[l * 2 + 1];
        const float ox = op[pt * 2 + 0], oy = op[pt * 2 + 1];
        const float invW = 1.0f / (float)W;
        const float xx = (rx + ox * invW) * (float)W - 0.5f;
        const float yy = (ry + oy * invW) * (float)W - 0.5f;
        const float x0f = floorf(xx), y0f = floorf(yy);
        const float dx = xx - x0f, dy = yy - y0f;
        const int xi = (int)x0f + (corner & 1);
        const int yi = (int)y0f + (corner >> 1);
        const float wx = (corner & 1) ? dx : 1.f - dx;
        const float wy = (corner >> 1) ? dy : 1.f - dy;
        const float wgt = __expf(lgp[pt] - mx) * inv * wx * wy;

        if (xi >= 0 && xi < W && yi >= 0 && yi < W) {
            const uint4* p = (const uint4*)(vbb + (size_t)(st + yi * W + xi) * DV) + ch4;
            uint4 v = *p;
            const __nv_bfloat162* h2 = (const __nv_bfloat162*)&v;
            #pragma unroll
            for (int j = 0; j < 4; j++) {
                float2 f = __bfloat1622float2(h2[j]);
                acc[2 * j]     = fmaf(wgt, f.x, acc[2 * j]);
                acc[2 * j + 1] = fmaf(wgt, f.y, acc[2 * j + 1]);
            }
        }
    }

    // reduce over the 8 corner slots (lanes xor 4,8,16 share ch4)
    #pragma unroll
    for (int o = 4; o <= 16; o <<= 1)
        #pragma unroll
        for (int j = 0; j < 8; j++)
            acc[j] += __shfl_xor_sync(0xffffffffu, acc[j], o);

    if (cg == 0) {
        uint4 outv;
        uint32_t* ov = (uint32_t*)&outv;
        #pragma unroll
        for (int j = 0; j < 4; j++) {
            __nv_bfloat162 pk = __float22bfloat162_rn(
                make_float2(acc[2 * j], acc[2 * j + 1]));
            ov[j] = *(uint32_t*)&pk;
        }
        *(uint4*)(attn + (size_t)gw * DH + ch4 * 8) = outv;
    }
}

// ---------------- launch ----------------
extern "C" void kernel_launch(void* const* d_in, const int* in_sizes, int n_in,
                              void* d_out, int out_size) {
    const float* q      = (const float*)d_in[0];
    const float* refp   = (const float*)d_in[1];
    const float* kv     = (const float*)d_in[2];
    const float* ln1w   = (const float*)d_in[5];
    const float* ln1b   = (const float*)d_in[6];
    const float* ln2w   = (const float*)d_in[7];
    const float* ln2b   = (const float*)d_in[8];
    const float* gamma  = (const float*)d_in[9];
    const float* w_off  = (const float*)d_in[10];
    const float* b_off  = (const float*)d_in[11];
    const float* w_aw   = (const float*)d_in[12];
    const float* b_aw   = (const float*)d_in[13];
    const float* w_val  = (const float*)d_in[14];
    const float* b_val  = (const float*)d_in[15];
    const float* w_out  = (const float*)d_in[16];
    const float* b_out  = (const float*)d_in[17];
    float* out = (float*)d_out;

    __nv_bfloat16 *gqn, *gkvn, *gv, *gattn, *gwv, *gwc, *gwo;
    float *goffaw, *gbc;
    cudaGetSymbolAddress((void**)&gqn,    g_qn);
    cudaGetSymbolAddress((void**)&gkvn,   g_kvn);
    cudaGetSymbolAddress((void**)&gv,     g_value);
    cudaGetSymbolAddress((void**)&goffaw, g_offaw);
    cudaGetSymbolAddress((void**)&gattn,  g_attn);
    cudaGetSymbolAddress((void**)&gwv,    g_wv);
    cudaGetSymbolAddress((void**)&gwc,    g_wc);
    cudaGetSymbolAddress((void**)&gwo,    g_wo);
    cudaGetSymbolAddress((void**)&gbc,    g_bc);

    static cudaStream_t s_side = nullptr;
    static cudaEvent_t ev_fork = nullptr, ev_join = nullptr;
    if (!s_side) {
        cudaStreamCreateWithFlags(&s_side, cudaStreamNonBlocking);
        cudaEventCreateWithFlags(&ev_fork, cudaEventDisableTiming);
        cudaEventCreateWithFlags(&ev_join, cudaEventDisableTiming);
        cudaFuncSetAttribute(hgemm_kernel<0>,
            cudaFuncAttributeMaxDynamicSharedMemorySize, SMEM_BYTES);
        cudaFuncSetAttribute(hgemm_kernel<1>,
            cudaFuncAttributeMaxDynamicSharedMemorySize, SMEM_BYTES);
        cudaFuncSetAttribute(hgemm_kernel<2>,
            cudaFuncAttributeMaxDynamicSharedMemorySize, SMEM_BYTES);
    }

    const int Mq  = BB * LQ;    // 16384
    const int Mkv = BB * LKV;   // 86016

    cudaEventRecord(ev_fork, 0);
    cudaStreamWaitEvent(s_side, ev_fork, 0);

    // ---- side chain: q path + weight prep for offaw/out ----
    ln_bf16_kernel<<<Mq, 192, 0, s_side>>>(q, gqn, ln1w, ln1b);
    pack_kernel<<<(EMBED * NPK + 255) / 256, 256, 0, s_side>>>(
        w_off, w_aw, b_off, b_aw, gwc, gbc);
    cvt_kernel<<<(DV * EMBED + 255) / 256, 256, 0, s_side>>>(w_out, gwo, DV * EMBED);
    hgemm_kernel<0><<<dim3((NPK + 127) / 128, Mq / 128), 256, SMEM_BYTES, s_side>>>(
        gqn, gwc, goffaw, Mq, NPK, EMBED, gbc, nullptr, nullptr);
    cudaEventRecord(ev_join, s_side);

    // ---- main chain: kv path ----
    ln_bf16_kernel<<<Mkv, 192>>>(kv, gkvn, ln2w, ln2b);
    cvt_kernel<<<(EMBED * DV + 255) / 256, 256>>>(w_val, gwv, EMBED * DV);
    hgemm_kernel<2><<<dim3(DV / 128, Mkv / 128), 256, SMEM_BYTES>>>(
        gkvn, gwv, gv, Mkv, DV, EMBED, b_val, nullptr, nullptr);

    cudaStreamWaitEvent(0, ev_join, 0);

    // ---- joined: sampling + output projection ----
    sample_kernel<<<(BB * LQ * NH) / 8, 256>>>(gv, goffaw, refp, gattn);
    hgemm_kernel<1><<<dim3(EMBED / 128, Mq / 128), 256, SMEM_BYTES>>>(
        gattn, gwo, out, Mq, EMBED, DV, b_out, q, gamma);
}